// round 1
// baseline (speedup 1.0000x reference)
#include <cuda_runtime.h>
#include <cstdint>

// Layout constants from the reference
// MARK_AX=0, OP_MUL=1, ALU_LO=16, ALU_HI=32, AX_CARRY_LO=48, AX_CARRY_HI=64,
// OUTPUT_LO=80, OUTPUT_HI=96, BD_DIM=128, GE_DIM=64, HID=256, RESULT=40, OPCODE idx in GE = 2+27 = 29

__global__ void __launch_bounds__(256, 8)
byte_mul_kernel(const float* __restrict__ x,
                const float* __restrict__ W1,
                const float* __restrict__ b1,
                const float* __restrict__ W2,
                const float* __restrict__ b2,
                float* __restrict__ out,
                int n_tokens)
{
    const unsigned FULL = 0xffffffffu;
    int warp_global = (blockIdx.x * blockDim.x + threadIdx.x) >> 5;
    int lane = threadIdx.x & 31;
    if (warp_global >= n_tokens) return;

    const float4* __restrict__ xin = reinterpret_cast<const float4*>(x) + (size_t)warp_global * 32;
    float4*       __restrict__ yout = reinterpret_cast<float4*>(out) + (size_t)warp_global * 32;

    float4 v = xin[lane];  // elements [4*lane .. 4*lane+3] of this token

    // --- mask: x[0] >= 0.5 && x[1] >= 0.5 (both live in lane 0's .x/.y) ---
    float m0 = __shfl_sync(FULL, v.x, 0);
    float m1 = __shfl_sync(FULL, v.y, 0);
    bool active = (m0 >= 0.5f) && (m1 >= 0.5f);

    if (!active) {
        yout[lane] = v;   // pure copy
        return;
    }

    // --- argmax over the four 16-element nibble segments ---
    // segment [16,32) -> lanes 4..7, [32,48) -> 8..11, [48,64) -> 12..15, [64,80) -> 16..19
    // local argmax among this lane's 4 components (first-max wins: strict >)
    float best = v.x; int bidx = 0;
    if (v.y > best) { best = v.y; bidx = 1; }
    if (v.z > best) { best = v.z; bidx = 2; }
    if (v.w > best) { best = v.w; bidx = 3; }
    int gidx = ((lane & 3) << 2) | bidx;  // index within this lane's 16-elem segment

    // butterfly reduce within each aligned quad of lanes (stays inside segment)
    #pragma unroll
    for (int off = 1; off <= 2; off <<= 1) {
        float ob = __shfl_xor_sync(FULL, best, off);
        int   oi = __shfl_xor_sync(FULL, gidx, off);
        if (ob > best || (ob == best && oi < gidx)) { best = ob; gidx = oi; }
    }

    int a_lo = __shfl_sync(FULL, gidx, 4);
    int a_hi = __shfl_sync(FULL, gidx, 8);
    int b_lo = __shfl_sync(FULL, gidx, 12);
    int b_hi = __shfl_sync(FULL, gidx, 16);

    float fa = (float)(a_lo | (a_hi << 4));  // byte_a
    float fb = (float)(b_lo | (b_hi << 4));  // byte_b

    // --- tiny MLP, position 0 only, 3-sparse input ---
    // h_j = relu(fa*W1[0,j] + fb*W1[1,j] + W1[29,j] + b1[j])
    // y   = sum_j h_j * W2[j,40] + b2[40]
    float acc = 0.0f;
    int jbase = lane << 3;  // 8 hidden units per lane
    #pragma unroll
    for (int i = 0; i < 8; i++) {
        int j = jbase + i;
        float c = W1[29 * 256 + j] + b1[j];
        float h = fmaf(fa, W1[j], fmaf(fb, W1[256 + j], c));
        h = fmaxf(h, 0.0f);
        acc = fmaf(h, W2[j * 64 + 40], acc);
    }
    #pragma unroll
    for (int off = 16; off; off >>= 1)
        acc += __shfl_xor_sync(FULL, acc, off);
    acc += b2[40];

    int res = ((int)rintf(acc)) & 255;   // rintf == round-half-even == jnp.round
    int r_lo = res & 15;
    int r_hi = res >> 4;

    // --- scatter +2.0 at OUTPUT_LO + r_lo (elem 80+r_lo) and OUTPUT_HI + r_hi (elem 96+r_hi) ---
    int e_lo = 80 + r_lo;
    int e_hi = 96 + r_hi;
    int base = lane << 2;
    float* vc = reinterpret_cast<float*>(&v);
    if (e_lo >= base && e_lo < base + 4) vc[e_lo - base] += 2.0f;
    if (e_hi >= base && e_hi < base + 4) vc[e_hi - base] += 2.0f;

    yout[lane] = v;
}

extern "C" void kernel_launch(void* const* d_in, const int* in_sizes, int n_in,
                              void* d_out, int out_size)
{
    const float* x  = (const float*)d_in[0];  // [8, 8192, 128]
    const float* W1 = (const float*)d_in[1];  // [64, 256]
    const float* b1 = (const float*)d_in[2];  // [256]
    const float* W2 = (const float*)d_in[3];  // [256, 64]
    const float* b2 = (const float*)d_in[4];  // [64]
    float* out = (float*)d_out;

    int n_tokens = in_sizes[0] / 128;         // 65536
    int warps_per_block = 8;                  // 256 threads
    int blocks = (n_tokens + warps_per_block - 1) / warps_per_block;

    byte_mul_kernel<<<blocks, warps_per_block * 32>>>(x, W1, b1, W2, b2, out, n_tokens);
}

// round 3
// speedup vs baseline: 2.7186x; 2.7186x over previous
#include <cuda_runtime.h>
#include <cstdint>

// Layout: MARK_AX=0, OP_MUL=1, ALU_LO=16, ALU_HI=32, AX_CARRY_LO=48, AX_CARRY_HI=64,
// OUTPUT_LO=80, OUTPUT_HI=96, BD_DIM=128. GE pos-0 input is 3-sparse:
//   idx0=byte_a, idx1=byte_b, idx29=1.0  -> h_j = relu(a*W1[0,j]+b*W1[1,j]+W1[29,j]+b1[j])
//   y_RESULT = sum_j h_j * W2[j,40] + b2[40]
// Per-j coefficients packed once per launch into g_coeff[j] = (W1[0,j], W1[1,j],
// W1[29,j]+b1[j], W2[j,40]) so the hot kernel only does coalesced L1-hot loads.

__device__ float4 g_coeff[256];
__device__ float  g_b2_40;

__global__ void prep_kernel(const float* __restrict__ W1,
                            const float* __restrict__ b1,
                            const float* __restrict__ W2,
                            const float* __restrict__ b2)
{
    int j = threadIdx.x;  // 256 threads
    g_coeff[j] = make_float4(W1[j],
                             W1[256 + j],
                             W1[29 * 256 + j] + b1[j],
                             W2[j * 64 + 40]);
    if (j == 0) g_b2_40 = b2[40];
}

__global__ void __launch_bounds__(256, 6)
byte_mul_kernel(const float* __restrict__ x,
                float* __restrict__ out,
                int n_tokens)
{
    const unsigned FULL = 0xffffffffu;
    int warp_global = (blockIdx.x * blockDim.x + threadIdx.x) >> 5;
    int lane = threadIdx.x & 31;
    if (warp_global >= n_tokens) return;

    const float4* __restrict__ xin  = reinterpret_cast<const float4*>(x)   + (size_t)warp_global * 32;
    float4*       __restrict__ yout = reinterpret_cast<float4*>(out)       + (size_t)warp_global * 32;

    float4 v = xin[lane];  // elements [4*lane .. 4*lane+3] of this token

    // mask: x[0] >= 0.5 && x[1] >= 0.5 (lane 0 holds both) — uniform per warp
    float m0 = __shfl_sync(FULL, v.x, 0);
    float m1 = __shfl_sync(FULL, v.y, 0);
    bool active = (m0 >= 0.5f) && (m1 >= 0.5f);

    if (!active) {
        yout[lane] = v;   // pure copy (75% of tokens)
        return;
    }

    // --- argmax over four 16-elem segments: [16,32)->lanes4..7, [32,48)->8..11,
    //     [48,64)->12..15, [64,80)->16..19. Reduce within aligned lane quads. ---
    float best = v.x; int bidx = 0;
    if (v.y > best) { best = v.y; bidx = 1; }
    if (v.z > best) { best = v.z; bidx = 2; }
    if (v.w > best) { best = v.w; bidx = 3; }
    int gidx = ((lane & 3) << 2) | bidx;

    #pragma unroll
    for (int off = 1; off <= 2; off <<= 1) {
        float ob = __shfl_xor_sync(FULL, best, off);
        int   oi = __shfl_xor_sync(FULL, gidx, off);
        if (ob > best || (ob == best && oi < gidx)) { best = ob; gidx = oi; }
    }

    int a_lo = __shfl_sync(FULL, gidx, 4);
    int a_hi = __shfl_sync(FULL, gidx, 8);
    int b_lo = __shfl_sync(FULL, gidx, 12);
    int b_hi = __shfl_sync(FULL, gidx, 16);

    float fa = (float)(a_lo | (a_hi << 4));
    float fb = (float)(b_lo | (b_hi << 4));

    // --- MLP from packed coefficients: j = lane + 32*i → coalesced LDG.128, L1-hot ---
    float acc = 0.0f;
    #pragma unroll
    for (int i = 0; i < 8; i++) {
        float4 c = __ldg(&g_coeff[lane + 32 * i]);
        float h = fmaf(fa, c.x, fmaf(fb, c.y, c.z));
        h = fmaxf(h, 0.0f);
        acc = fmaf(h, c.w, acc);
    }
    #pragma unroll
    for (int off = 16; off; off >>= 1)
        acc += __shfl_xor_sync(FULL, acc, off);
    acc += g_b2_40;

    int res = ((int)rintf(acc)) & 255;   // rintf == round-half-even == jnp.round
    int e_lo = 80 + (res & 15);
    int e_hi = 96 + (res >> 4);

    int base = lane << 2;
    float* vc = reinterpret_cast<float*>(&v);
    if (e_lo >= base && e_lo < base + 4) vc[e_lo - base] += 2.0f;
    if (e_hi >= base && e_hi < base + 4) vc[e_hi - base] += 2.0f;

    yout[lane] = v;
}

extern "C" void kernel_launch(void* const* d_in, const int* in_sizes, int n_in,
                              void* d_out, int out_size)
{
    const float* x  = (const float*)d_in[0];  // [8, 8192, 128]
    const float* W1 = (const float*)d_in[1];  // [64, 256]
    const float* b1 = (const float*)d_in[2];  // [256]
    const float* W2 = (const float*)d_in[3];  // [256, 64]
    const float* b2 = (const float*)d_in[4];  // [64]
    float* out = (float*)d_out;

    int n_tokens = in_sizes[0] / 128;         // 65536

    prep_kernel<<<1, 256>>>(W1, b1, W2, b2);

    int warps_per_block = 8;                  // 256 threads
    int blocks = (n_tokens + warps_per_block - 1) / warps_per_block;
    byte_mul_kernel<<<blocks, warps_per_block * 32>>>(x, out, n_tokens);
}